// round 9
// baseline (speedup 1.0000x reference)
#include <cuda_runtime.h>
#include <cuda_fp16.h>
#include <cstdint>

#define DEV __device__ __forceinline__

// problem dims
#define N_IMG 256
#define D_INF 768
#define D_HID 768
#define D_OUTF 512
#define M_GAL 100000
#define TOPK 5

// scratch (no cudaMalloc allowed)
__device__ __half g_Ahi1[N_IMG*D_INF];
__device__ __half g_Alo1[N_IMG*D_INF];
__device__ __half g_Ahi2[N_IMG*D_HID];
__device__ __half g_Alo2[N_IMG*D_HID];
__device__ float  g_IMG [N_IMG*D_OUTF];
__device__ __half g_AN  [N_IMG*D_OUTF];
// topk scratch
__device__ float g_pmax[100];
__device__ float g_psum[100];
__device__ int   g_pidx[100*TOPK];
__device__ float g_pval[100*TOPK];

DEV void cp16(void* s, const void* g){
  uint32_t sa = (uint32_t)__cvta_generic_to_shared(s);
  asm volatile("cp.async.cg.shared.global [%0], [%1], 16;" :: "r"(sa), "l"(g));
}
DEV void cp_commit(){ asm volatile("cp.async.commit_group;"); }
DEV void cp_wait0(){ asm volatile("cp.async.wait_group 0;"); }
DEV void cp_wait1(){ asm volatile("cp.async.wait_group 1;"); }

DEV void ldsm4(uint32_t* d, const void* p){
  uint32_t a=(uint32_t)__cvta_generic_to_shared(p);
  asm volatile("ldmatrix.sync.aligned.m8n8.x4.shared.b16 {%0,%1,%2,%3}, [%4];"
    : "=r"(d[0]),"=r"(d[1]),"=r"(d[2]),"=r"(d[3]) : "r"(a));
}
DEV void mma_fp16(float* c, const uint32_t* a, const uint32_t* b){
  asm volatile("mma.sync.aligned.m16n8k16.row.col.f32.f16.f16.f32 "
    "{%0,%1,%2,%3}, {%4,%5,%6,%7}, {%8,%9}, {%0,%1,%2,%3};"
    : "+f"(c[0]),"+f"(c[1]),"+f"(c[2]),"+f"(c[3])
    : "r"(a[0]),"r"(a[1]),"r"(a[2]),"r"(a[3]),"r"(b[0]),"r"(b[1]));
}

// =========== MLP GEMM (round-5 exact): 3-term fp16, BM=64 BN=64 BK=64, 2-stage ===========
template<bool RELU, bool SPLIT>
__global__ __launch_bounds__(256, 2)
void hgemm3(const __half* __restrict__ Ahi, const __half* __restrict__ Alo,
            const float* __restrict__ B, const float* __restrict__ bias,
            float* __restrict__ Cf, __half* __restrict__ Chi, __half* __restrict__ Clo,
            int Ntot, int K){
  constexpr int SABB = 144;
  constexpr int ABYTES = 64*SABB;
  constexpr int OB     = 2*ABYTES;
  constexpr int BBYTES = 64*SABB;
  constexpr int STAGE  = OB + 2*BBYTES;        // 36864

  extern __shared__ __align__(16) char sm[];
  const int tid = threadIdx.x, lane = tid & 31, warp = tid >> 5;
  const int wm = (warp & 1) * 32, wn = (warp >> 1) * 16;
  const int m0 = blockIdx.x * 64, n0 = blockIdx.y * 64;
  const int nch = K / 64;

  float acc[2][2][4];
#pragma unroll
  for (int a=0;a<2;a++)
#pragma unroll
    for (int b=0;b<2;b++)
#pragma unroll
      for (int c=0;c<4;c++) acc[a][b][c]=0.f;

  float4 breg[2][2];
  auto loadB = [&](int kb){
#pragma unroll
    for (int s=0;s<2;s++){
      int seg = tid + s*256;
      int row = seg >> 3, sc = seg & 7;
      const float4* p = reinterpret_cast<const float4*>(B + (size_t)(n0+row)*K + kb + sc*8);
      breg[s][0] = p[0]; breg[s][1] = p[1];
    }
  };
  auto stsB = [&](int buf){
#pragma unroll
    for (int s=0;s<2;s++){
      int seg = tid + s*256;
      int row = seg >> 3, sc = seg & 7;
      float f[8] = {breg[s][0].x,breg[s][0].y,breg[s][0].z,breg[s][0].w,
                    breg[s][1].x,breg[s][1].y,breg[s][1].z,breg[s][1].w};
      union { uint4 u; __half h[8]; } ph, pl;
#pragma unroll
      for (int e=0;e<8;e++){
        __half hh = __float2half_rn(f[e]);
        ph.h[e] = hh;
        pl.h[e] = __float2half_rn(f[e] - __half2float(hh));
      }
      char* dst = sm + buf*STAGE + OB + row*SABB + sc*16;
      *reinterpret_cast<uint4*>(dst)          = ph.u;
      *reinterpret_cast<uint4*>(dst + BBYTES) = pl.u;
    }
  };
  auto cpA = [&](int buf, int kb){
#pragma unroll
    for (int s=0;s<2;s++){
      int seg = tid + s*256;
      int row = seg >> 3, sc = seg & 7;
      size_t go = (size_t)(m0 + row)*K + kb + sc*8;
      char* d = sm + buf*STAGE + row*SABB + sc*16;
      cp16(d,          Ahi + go);
      cp16(d + ABYTES, Alo + go);
    }
  };
  auto do_mma = [&](int buf){
    char* sa  = sm + buf*STAGE;
    char* sbh = sa + OB;
    const int ar = lane & 15, ac = (lane >> 4) * 8;
    const int q = lane >> 3, rq = lane & 7;
    const int bro = ((q>>1)*8 + rq)*SABB + (q&1)*16;
#pragma unroll
    for (int ks=0; ks<4; ks++){
      const int kk = ks*16;
      uint32_t ah[2][4], al[2][4], bh[4], bl[4];
#pragma unroll
      for (int ms=0; ms<2; ms++){
        char* pa = sa + (wm + ms*16 + ar)*SABB + (kk + ac)*2;
        ldsm4(ah[ms], pa);
        ldsm4(al[ms], pa + ABYTES);
      }
      {
        char* pb = sbh + wn*SABB + kk*2 + bro;
        ldsm4(bh, pb);
        ldsm4(bl, pb + BBYTES);
      }
#pragma unroll
      for (int ms=0; ms<2; ms++)
#pragma unroll
        for (int ns=0; ns<2; ns++){
          mma_fp16(acc[ms][ns], ah[ms], bh + ns*2);
          mma_fp16(acc[ms][ns], al[ms], bh + ns*2);
          mma_fp16(acc[ms][ns], ah[ms], bl + ns*2);
        }
    }
  };

  loadB(0); stsB(0); cpA(0,0); cp_commit();
  for (int i=0; i<nch; i++){
    const int buf = i & 1;
    if (i+1 < nch) loadB((i+1)*64);
    cp_wait0();
    __syncthreads();
    if (i+1 < nch){ cpA(buf^1, (i+1)*64); cp_commit(); }
    do_mma(buf);
    if (i+1 < nch) stsB(buf^1);
  }

  const int gr = lane >> 2, gc = (lane & 3) * 2;
#pragma unroll
  for (int ms=0; ms<2; ms++)
#pragma unroll
    for (int ns=0; ns<2; ns++){
      int row = m0 + wm + ms*16 + gr;
      int col = n0 + wn + ns*8 + gc;
      float v0=acc[ms][ns][0], v1=acc[ms][ns][1], v2=acc[ms][ns][2], v3=acc[ms][ns][3];
      float c0=bias[col], c1=bias[col+1];
      v0+=c0; v1+=c1; v2+=c0; v3+=c1;
      if (RELU){ v0=fmaxf(v0,0.f); v1=fmaxf(v1,0.f); v2=fmaxf(v2,0.f); v3=fmaxf(v3,0.f); }
      if (SPLIT){
        __half h0=__float2half_rn(v0), h1=__float2half_rn(v1);
        __half h2=__float2half_rn(v2), h3=__float2half_rn(v3);
        *reinterpret_cast<__half2*>(&Chi[(size_t)row*Ntot + col])     = __halves2half2(h0,h1);
        *reinterpret_cast<__half2*>(&Chi[(size_t)(row+8)*Ntot + col]) = __halves2half2(h2,h3);
        *reinterpret_cast<__half2*>(&Clo[(size_t)row*Ntot + col]) =
            __halves2half2(__float2half_rn(v0-__half2float(h0)), __float2half_rn(v1-__half2float(h1)));
        *reinterpret_cast<__half2*>(&Clo[(size_t)(row+8)*Ntot + col]) =
            __halves2half2(__float2half_rn(v2-__half2float(h2)), __float2half_rn(v3-__half2float(h3)));
      } else {
        *reinterpret_cast<float2*>(&Cf[(size_t)row*Ntot + col])     = make_float2(v0,v1);
        *reinterpret_cast<float2*>(&Cf[(size_t)(row+8)*Ntot + col]) = make_float2(v2,v3);
      }
    }
}

// ===== big GEMM v2: fused conv one chunk AHEAD of mma; 3-slot cp.async ring + 2-slot f16 =====
__global__ __launch_bounds__(256, 2)
void hgemmBig(const __half* __restrict__ A, const float* __restrict__ B,
              float* __restrict__ C, int Ntot, int K){
  constexpr int SRS   = 80;                    // fp16 row stride (32 halfs + pad)
  constexpr int ARB   = 128*SRS;               // 10240 : A fp16 in ring slot
  constexpr int BF32B = 128*128;               // 16384 : B f32 in ring slot
  constexpr int RSLOT = ARB + BF32B;           // 26624
  constexpr int F16OFF= 3*RSLOT;               // 79872
  constexpr int F16B  = 128*SRS;               // 10240 per f16 slot (x2)
  // total smem = 79872 + 20480 = 100352
  constexpr int BK    = 32;

  extern __shared__ __align__(16) char sm[];
  const int tid = threadIdx.x, lane = tid & 31, warp = tid >> 5;
  const int wm = (warp & 1) * 64, wn = (warp >> 1) * 32;   // 2x4 warps, 64x32 tiles
  const int m0 = blockIdx.x * 128, n0 = blockIdx.y * 128;
  const int nch = K / BK;                      // 16

  float acc[4][4][4];
#pragma unroll
  for (int a=0;a<4;a++)
#pragma unroll
    for (int b=0;b<4;b++)
#pragma unroll
      for (int c=0;c<4;c++) acc[a][b][c]=0.f;

  auto issue = [&](int slot, int kb){
    char* sb = sm + slot*RSLOT;
    // A fp16: 128 rows x 4 x 16B = 512 segs (2/thread)
#pragma unroll
    for (int s=0;s<2;s++){
      int seg = tid + s*256;
      int row = seg >> 2, sc = seg & 3;
      cp16(sb + row*SRS + sc*16, A + (size_t)(m0 + row)*K + kb + sc*8);
    }
    // B f32: 128 rows x 8 x 16B = 1024 segs (4/thread)
#pragma unroll
    for (int s=0;s<4;s++){
      int seg = tid + s*256;
      int row = seg >> 3, sc = seg & 7;
      int gn = n0 + row; if (gn > Ntot-1) gn = Ntot-1;
      cp16(sb + ARB + row*128 + sc*16, B + (size_t)gn*K + kb + sc*4);
    }
    cp_commit();
  };
  auto conv = [&](int c){
    char* src = sm + (c%3)*RSLOT + ARB;
    char* dst = sm + F16OFF + (c&1)*F16B;
#pragma unroll
    for (int s=0;s<2;s++){
      int unit = tid + s*256;
      int row = unit >> 2, sc = unit & 3;
      const float4* p = reinterpret_cast<const float4*>(src + row*128 + sc*32);
      float4 a = p[0], b = p[1];
      union { uint4 u; __half2 h[4]; } o;
      o.h[0] = __floats2half2_rn(a.x, a.y);
      o.h[1] = __floats2half2_rn(a.z, a.w);
      o.h[2] = __floats2half2_rn(b.x, b.y);
      o.h[3] = __floats2half2_rn(b.z, b.w);
      *reinterpret_cast<uint4*>(dst + row*SRS + sc*16) = o.u;
    }
  };
  auto do_mma = [&](int c){
    char* sa = sm + (c%3)*RSLOT;                  // A fp16
    char* sb = sm + F16OFF + (c&1)*F16B;          // B fp16 (converted)
    const int ar = lane & 15, ac = (lane >> 4) * 8;
    const int q = lane >> 3, rq = lane & 7;
    const int bro = ((q>>1)*8 + rq)*SRS + (q&1)*16;
#pragma unroll
    for (int ks=0; ks<2; ks++){
      const int kk = ks*16;
      uint32_t af[4][4], bf[8];
#pragma unroll
      for (int ms=0; ms<4; ms++)
        ldsm4(af[ms], sa + (wm + ms*16 + ar)*SRS + (kk + ac)*2);
#pragma unroll
      for (int nsp=0; nsp<2; nsp++)
        ldsm4(bf + nsp*4, sb + (wn + nsp*16)*SRS + kk*2 + bro);
#pragma unroll
      for (int ms=0; ms<4; ms++)
#pragma unroll
        for (int ns=0; ns<4; ns++)
          mma_fp16(acc[ms][ns], af[ms], bf + ns*2);
    }
  };

  // prologue: 2 groups in flight, convert chunk 0
  issue(0, 0);
  issue(1, BK);
  cp_wait1();                 // group 0 complete (this thread)
  __syncthreads();            // all threads' group-0 parts visible
  conv(0);

  for (int i=0; i<nch; i++){
    __syncthreads();          // conv(i) STS visible to all; mma(i-1) retired everywhere
    if (i+2 < nch) issue((i+2)%3, (i+2)*BK);   // overwrites ring (i-1)%3 — safe post-sync
    do_mma(i);                // A ring i%3, Bf16 slot i&1
    if (i+1 < nch){
      if (i+2 < nch) cp_wait1(); else cp_wait0();   // group i+1 complete
      __syncthreads();        // cross-thread arrival of group i+1
      conv(i+1);              // ring (i+1)%3 -> f16 slot (i+1)&1 (mma(i) used slot i&1)
    }
  }

  const int gr = lane >> 2, gc = (lane & 3) * 2;
#pragma unroll
  for (int ms=0; ms<4; ms++)
#pragma unroll
    for (int ns=0; ns<4; ns++){
      int row = m0 + wm + ms*16 + gr;
      int col = n0 + wn + ns*8 + gc;
      if (col < Ntot){
        *reinterpret_cast<float2*>(&C[(size_t)row*Ntot + col])     = make_float2(acc[ms][ns][0], acc[ms][ns][1]);
        *reinterpret_cast<float2*>(&C[(size_t)(row+8)*Ntot + col]) = make_float2(acc[ms][ns][2], acc[ms][ns][3]);
      }
    }
}

// ---------------- small kernels ----------------
__global__ void split_k(const float* __restrict__ src, __half* __restrict__ hi,
                        __half* __restrict__ lo, int n){
  int i = blockIdx.x*256 + threadIdx.x;
  if (i < n){
    float x = src[i];
    __half h = __float2half_rn(x);
    hi[i] = h;
    lo[i] = __float2half_rn(x - __half2float(h));
  }
}

// warp-per-row normalize: no smem, shuffle reductions only
__global__ void rownorm_h(const float* __restrict__ img, const float* __restrict__ ls,
                          __half* __restrict__ outh){
  int warp = threadIdx.x >> 5, lane = threadIdx.x & 31;
  int row = blockIdx.x*8 + warp;
  float v[16]; float s = 0.f;
#pragma unroll
  for (int j=0;j<16;j++){ v[j] = img[row*D_OUTF + lane + j*32]; s += v[j]*v[j]; }
#pragma unroll
  for (int off=16; off>0; off>>=1) s += __shfl_xor_sync(0xffffffffu, s, off);
  float sc = expf(*ls) * rsqrtf(s);
#pragma unroll
  for (int j=0;j<16;j++)
    outh[row*D_OUTF + lane + j*32] = __float2half_rn(v[j]*sc);
}

// topk phase 1: 100 blocks x 256 threads over row 0 (1000 logits each)
__global__ void topk_p1(const float* __restrict__ logits){
  __shared__ float rv[256];
  __shared__ int   ri[256];
  __shared__ int   sel[TOPK];
  __shared__ float bmax_s;
  int t = threadIdx.x, b = blockIdx.x;
  int lo = b*1000, hi = lo + 1000;

  float m = -3.4e38f;
  for (int i = lo + t; i < hi; i += 256) m = fmaxf(m, logits[i]);
  rv[t] = m; __syncthreads();
  for (int s=128; s>0; s>>=1){ if (t<s) rv[t]=fmaxf(rv[t],rv[t+s]); __syncthreads(); }
  if (t==0) bmax_s = rv[0];
  __syncthreads();
  float bm = bmax_s;

  float sum = 0.f;
  for (int i = lo + t; i < hi; i += 256) sum += expf(logits[i] - bm);
  rv[t] = sum; __syncthreads();
  for (int s=128; s>0; s>>=1){ if (t<s) rv[t]+=rv[t+s]; __syncthreads(); }
  if (t==0){ g_pmax[b] = bm; g_psum[b] = rv[0]; }
  __syncthreads();

  for (int r = 0; r < TOPK; r++){
    float bv = -3.4e38f; int bi = 0x7fffffff;
    for (int i = lo + t; i < hi; i += 256){
      bool skip = false;
#pragma unroll
      for (int j = 0; j < TOPK; j++) if (j < r && sel[j] == i) skip = true;
      float v = logits[i];
      if (!skip && (v > bv || (v == bv && i < bi))){ bv = v; bi = i; }
    }
    rv[t] = bv; ri[t] = bi; __syncthreads();
    for (int s=128; s>0; s>>=1){
      if (t<s){
        if (rv[t+s] > rv[t] || (rv[t+s] == rv[t] && ri[t+s] < ri[t])){
          rv[t]=rv[t+s]; ri[t]=ri[t+s];
        }
      }
      __syncthreads();
    }
    if (t==0){ sel[r] = ri[0]; g_pidx[b*TOPK + r] = ri[0]; g_pval[b*TOPK + r] = rv[0]; }
    __syncthreads();
  }
}

// topk phase 2: merge 100 partials, write gps + probs tail
__global__ void topk_p2(const float* __restrict__ gps, float* __restrict__ out_tail){
  __shared__ float rv[512];
  __shared__ int   ri[512];
  __shared__ float gM_s, gS_s;
  int t = threadIdx.x;

  float m = (t < 100) ? g_pmax[t] : -3.4e38f;
  rv[t] = m; __syncthreads();
  for (int s=256; s>0; s>>=1){ if (t<s) rv[t]=fmaxf(rv[t],rv[t+s]); __syncthreads(); }
  if (t==0) gM_s = rv[0];
  __syncthreads();
  float M = gM_s;

  float sum = (t < 100) ? g_psum[t] * expf(g_pmax[t] - M) : 0.f;
  rv[t] = sum; __syncthreads();
  for (int s=256; s>0; s>>=1){ if (t<s) rv[t]+=rv[t+s]; __syncthreads(); }
  if (t==0) gS_s = rv[0];
  __syncthreads();
  float S = gS_s;

  float cv = (t < 100*TOPK) ? g_pval[t] : -3.4e38f;
  int   ci = (t < 100*TOPK) ? g_pidx[t] : 0x7fffffff;

  for (int r = 0; r < TOPK; r++){
    rv[t] = cv; ri[t] = ci; __syncthreads();
    for (int s=256; s>0; s>>=1){
      if (t<s){
        if (rv[t+s] > rv[t] || (rv[t+s] == rv[t] && ri[t+s] < ri[t])){
          rv[t]=rv[t+s]; ri[t]=ri[t+s];
        }
      }
      __syncthreads();
    }
    if (t == 0){
      int gi = ri[0];
      out_tail[2*r]   = gps[2*gi];
      out_tail[2*r+1] = gps[2*gi+1];
      out_tail[2*TOPK + r] = expf(rv[0] - M) / S;
    }
    __syncthreads();
    if (ci == ri[0]) cv = -3.4e38f;
    __syncthreads();
  }
}

extern "C" void kernel_launch(void* const* d_in, const int* in_sizes, int n_in,
                              void* d_out, int out_size){
  const float* img_feats   = (const float*)d_in[0];
  const float* w1          = (const float*)d_in[1];
  const float* b1          = (const float*)d_in[2];
  const float* w2          = (const float*)d_in[3];
  const float* b2          = (const float*)d_in[4];
  const float* logit_scale = (const float*)d_in[5];
  const float* loc_feats   = (const float*)d_in[6];
  const float* gps         = (const float*)d_in[7];
  float* out = (float*)d_out;

  void *ahi1,*alo1,*ahi2,*alo2,*imgb,*an;
  cudaGetSymbolAddress(&ahi1, g_Ahi1);
  cudaGetSymbolAddress(&alo1, g_Alo1);
  cudaGetSymbolAddress(&ahi2, g_Ahi2);
  cudaGetSymbolAddress(&alo2, g_Alo2);
  cudaGetSymbolAddress(&imgb, g_IMG);
  cudaGetSymbolAddress(&an,   g_AN);

  cudaFuncSetAttribute(hgemm3<true,true>,   cudaFuncAttributeMaxDynamicSharedMemorySize, 73728);
  cudaFuncSetAttribute(hgemm3<false,false>, cudaFuncAttributeMaxDynamicSharedMemorySize, 73728);
  cudaFuncSetAttribute(hgemmBig,            cudaFuncAttributeMaxDynamicSharedMemorySize, 100352);

  // 1) split input to fp16 hi/lo
  split_k<<<(N_IMG*D_INF+255)/256,256>>>(img_feats, (__half*)ahi1, (__half*)alo1, N_IMG*D_INF);
  // 2) H = relu(X W1^T + b1), epilogue writes fp16 hi/lo split directly
  hgemm3<true,true><<<dim3(4, D_HID/64), 256, 73728>>>(
      (__half*)ahi1, (__half*)alo1, w1, b1, nullptr, (__half*)ahi2, (__half*)alo2, D_HID, D_INF);
  // 3) IMG = H W2^T + b2 (f32 out)
  hgemm3<false,false><<<dim3(4, D_OUTF/64), 256, 73728>>>(
      (__half*)ahi2, (__half*)alo2, w2, b2, (float*)imgb, nullptr, nullptr, D_OUTF, D_HID);
  // 4) normalize rows, fold in exp(logit_scale) -> single fp16 (warp-per-row)
  rownorm_h<<<N_IMG/8,256>>>((const float*)imgb, logit_scale, (__half*)an);
  // 5) logits = (s*img_n) @ loc_feats^T ; fused f32->f16 conversion, conv-ahead pipeline
  hgemmBig<<<dim3(2, (M_GAL+127)/128), 256, 100352>>>(
      (__half*)an, loc_feats, out, M_GAL, D_OUTF);
  // 6) row-0 softmax + top-5
  topk_p1<<<100,256>>>(out);
  topk_p2<<<1,512>>>(gps, out + (size_t)N_IMG*M_GAL);
}

// round 12
// speedup vs baseline: 1.0094x; 1.0094x over previous
#include <cuda_runtime.h>
#include <cuda_fp16.h>
#include <cstdint>

#define DEV __device__ __forceinline__

// problem dims
#define N_IMG 256
#define D_INF 768
#define D_HID 768
#define D_OUTF 512
#define M_GAL 100000
#define TOPK 5

// scratch (no cudaMalloc allowed)
__device__ __half g_Ahi2[N_IMG*D_HID];
__device__ __half g_Alo2[N_IMG*D_HID];
__device__ float  g_IMG [N_IMG*D_OUTF];
__device__ __half g_AN  [N_IMG*D_OUTF];
// topk scratch
__device__ float g_pmax[100];
__device__ float g_psum[100];
__device__ int   g_pidx[100*TOPK];
__device__ float g_pval[100*TOPK];

DEV void cp16(void* s, const void* g){
  uint32_t sa = (uint32_t)__cvta_generic_to_shared(s);
  asm volatile("cp.async.cg.shared.global [%0], [%1], 16;" :: "r"(sa), "l"(g));
}
DEV void cp_commit(){ asm volatile("cp.async.commit_group;"); }
DEV void cp_wait0(){ asm volatile("cp.async.wait_group 0;"); }
DEV void cp_wait1(){ asm volatile("cp.async.wait_group 1;"); }

DEV void ldsm4(uint32_t* d, const void* p){
  uint32_t a=(uint32_t)__cvta_generic_to_shared(p);
  asm volatile("ldmatrix.sync.aligned.m8n8.x4.shared.b16 {%0,%1,%2,%3}, [%4];"
    : "=r"(d[0]),"=r"(d[1]),"=r"(d[2]),"=r"(d[3]) : "r"(a));
}
DEV void mma_fp16(float* c, const uint32_t* a, const uint32_t* b){
  asm volatile("mma.sync.aligned.m16n8k16.row.col.f32.f16.f16.f32 "
    "{%0,%1,%2,%3}, {%4,%5,%6,%7}, {%8,%9}, {%0,%1,%2,%3};"
    : "+f"(c[0]),"+f"(c[1]),"+f"(c[2]),"+f"(c[3])
    : "r"(a[0]),"r"(a[1]),"r"(a[2]),"r"(a[3]),"r"(b[0]),"r"(b[1]));
}

// ===== MLP GEMM: 3-term fp16, BM=32 BN=64 BK=64, 2-stage =====
// A_F32: A read as f32 + converted in-kernel (removes split_k prepass).
template<bool A_F32, bool RELU, bool SPLIT>
__global__ __launch_bounds__(256, 2)
void mlpgemm(const float* __restrict__ Af, const __half* __restrict__ Ahi, const __half* __restrict__ Alo,
             const float* __restrict__ B, const float* __restrict__ bias,
             float* __restrict__ Cf, __half* __restrict__ Chi, __half* __restrict__ Clo,
             int Ntot, int K){
  constexpr int SABB = 144;
  constexpr int ABY  = 32*SABB;      // 4608 per A matrix (hi or lo)
  constexpr int OB   = 2*ABY;        // 9216
  constexpr int BBY  = 64*SABB;      // 9216
  constexpr int STAGE= OB + 2*BBY;   // 27648 ; x2 stages = 55296

  extern __shared__ __align__(16) char sm[];
  const int tid = threadIdx.x, lane = tid & 31, warp = tid >> 5;
  const int wm = (warp & 1) * 16, wn = (warp >> 1) * 16;   // 2x4 warps, 16x16 tiles
  const int m0 = blockIdx.x * 32, n0 = blockIdx.y * 64;
  const int nch = K / 64;

  float acc[2][4];
#pragma unroll
  for (int b=0;b<2;b++)
#pragma unroll
    for (int c=0;c<4;c++) acc[b][c]=0.f;

  float4 breg[2][2];
  float4 areg[2];
  auto loadB = [&](int kb){
#pragma unroll
    for (int s=0;s<2;s++){
      int seg = tid + s*256;                 // 512 units of 8 f32 (64 rows x 8)
      int row = seg >> 3, sc = seg & 7;
      const float4* p = reinterpret_cast<const float4*>(B + (size_t)(n0+row)*K + kb + sc*8);
      breg[s][0] = p[0]; breg[s][1] = p[1];
    }
  };
  auto loadA = [&](int kb){                  // A_F32 only: 256 units (32 rows x 8)
    int row = tid >> 3, sc = tid & 7;
    const float4* p = reinterpret_cast<const float4*>(Af + (size_t)(m0+row)*K + kb + sc*8);
    areg[0] = p[0]; areg[1] = p[1];
  };
  auto split8 = [&](const float4& a, const float4& b, uint4& uh, uint4& ul){
    float f[8] = {a.x,a.y,a.z,a.w,b.x,b.y,b.z,b.w};
    union { uint4 u; __half h[8]; } ph, pl;
#pragma unroll
    for (int e=0;e<8;e++){
      __half hh = __float2half_rn(f[e]);
      ph.h[e] = hh;
      pl.h[e] = __float2half_rn(f[e] - __half2float(hh));
    }
    uh = ph.u; ul = pl.u;
  };
  auto stsB = [&](int buf){
#pragma unroll
    for (int s=0;s<2;s++){
      int seg = tid + s*256;
      int row = seg >> 3, sc = seg & 7;
      uint4 uh, ul;
      split8(breg[s][0], breg[s][1], uh, ul);
      char* dst = sm + buf*STAGE + OB + row*SABB + sc*16;
      *reinterpret_cast<uint4*>(dst)       = uh;
      *reinterpret_cast<uint4*>(dst + BBY) = ul;
    }
  };
  auto stsA = [&](int buf){                  // A_F32 only
    int row = tid >> 3, sc = tid & 7;
    uint4 uh, ul;
    split8(areg[0], areg[1], uh, ul);
    char* dst = sm + buf*STAGE + row*SABB + sc*16;
    *reinterpret_cast<uint4*>(dst)       = uh;
    *reinterpret_cast<uint4*>(dst + ABY) = ul;
  };
  auto cpA = [&](int buf, int kb){
    // FIX (round-10 bug): 32 rows x 8 x 16B segments = full 128B/row.
    // Round 10 loaded only 4 segments/row -> half of A was stale smem.
    int row = tid >> 3, sc = tid & 7;
    size_t go = (size_t)(m0 + row)*K + kb + sc*8;
    char* d = sm + buf*STAGE + row*SABB + sc*16;
    cp16(d,       Ahi + go);
    cp16(d + ABY, Alo + go);
  };
  auto do_mma = [&](int buf){
    char* sa  = sm + buf*STAGE;
    char* sbh = sa + OB;
    const int ar = lane & 15, ac = (lane >> 4) * 8;
    const int q = lane >> 3, rq = lane & 7;
    const int bro = ((q>>1)*8 + rq)*SABB + (q&1)*16;
#pragma unroll
    for (int ks=0; ks<4; ks++){
      const int kk = ks*16;
      uint32_t ah[4], al[4], bh[4], bl[4];
      char* pa = sa + (wm + ar)*SABB + (kk + ac)*2;
      ldsm4(ah, pa);
      ldsm4(al, pa + ABY);
      char* pb = sbh + wn*SABB + kk*2 + bro;
      ldsm4(bh, pb);
      ldsm4(bl, pb + BBY);
#pragma unroll
      for (int ns=0; ns<2; ns++){
        mma_fp16(acc[ns], ah, bh + ns*2);
        mma_fp16(acc[ns], al, bh + ns*2);
        mma_fp16(acc[ns], ah, bl + ns*2);
      }
    }
  };

  // prologue
  loadB(0); if (A_F32) loadA(0);
  stsB(0);  if (A_F32) stsA(0);
  if (!A_F32){ cpA(0, 0); cp_commit(); }

  for (int i=0; i<nch; i++){
    const int buf = i & 1;
    if (i+1 < nch){ loadB((i+1)*64); if (A_F32) loadA((i+1)*64); }
    if (!A_F32) cp_wait0();
    __syncthreads();
    if (!A_F32 && i+1 < nch){ cpA(buf^1, (i+1)*64); cp_commit(); }
    do_mma(buf);
    if (i+1 < nch){ stsB(buf^1); if (A_F32) stsA(buf^1); }
  }

  const int gr = lane >> 2, gc = (lane & 3) * 2;
#pragma unroll
  for (int ns=0; ns<2; ns++){
    int row = m0 + wm + gr;
    int col = n0 + wn + ns*8 + gc;
    float v0=acc[ns][0], v1=acc[ns][1], v2=acc[ns][2], v3=acc[ns][3];
    float c0=bias[col], c1=bias[col+1];
    v0+=c0; v1+=c1; v2+=c0; v3+=c1;
    if (RELU){ v0=fmaxf(v0,0.f); v1=fmaxf(v1,0.f); v2=fmaxf(v2,0.f); v3=fmaxf(v3,0.f); }
    if (SPLIT){
      __half h0=__float2half_rn(v0), h1=__float2half_rn(v1);
      __half h2=__float2half_rn(v2), h3=__float2half_rn(v3);
      *reinterpret_cast<__half2*>(&Chi[(size_t)row*Ntot + col])     = __halves2half2(h0,h1);
      *reinterpret_cast<__half2*>(&Chi[(size_t)(row+8)*Ntot + col]) = __halves2half2(h2,h3);
      *reinterpret_cast<__half2*>(&Clo[(size_t)row*Ntot + col]) =
          __halves2half2(__float2half_rn(v0-__half2float(h0)), __float2half_rn(v1-__half2float(h1)));
      *reinterpret_cast<__half2*>(&Clo[(size_t)(row+8)*Ntot + col]) =
          __halves2half2(__float2half_rn(v2-__half2float(h2)), __float2half_rn(v3-__half2float(h3)));
    } else {
      *reinterpret_cast<float2*>(&Cf[(size_t)row*Ntot + col])     = make_float2(v0,v1);
      *reinterpret_cast<float2*>(&Cf[(size_t)(row+8)*Ntot + col]) = make_float2(v2,v3);
    }
  }
}

// ===== big GEMM (round-9 proven): fused conv ahead of mma; 3-slot ring + 2-slot f16 =====
__global__ __launch_bounds__(256, 2)
void hgemmBig(const __half* __restrict__ A, const float* __restrict__ B,
              float* __restrict__ C, int Ntot, int K){
  constexpr int SRS   = 80;
  constexpr int ARB   = 128*SRS;               // 10240
  constexpr int BF32B = 128*128;               // 16384
  constexpr int RSLOT = ARB + BF32B;           // 26624
  constexpr int F16OFF= 3*RSLOT;               // 79872
  constexpr int F16B  = 128*SRS;               // 10240 x2
  constexpr int BK    = 32;

  extern __shared__ __align__(16) char sm[];
  const int tid = threadIdx.x, lane = tid & 31, warp = tid >> 5;
  const int wm = (warp & 1) * 64, wn = (warp >> 1) * 32;
  const int m0 = blockIdx.x * 128, n0 = blockIdx.y * 128;
  const int nch = K / BK;                      // 16

  float acc[4][4][4];
#pragma unroll
  for (int a=0;a<4;a++)
#pragma unroll
    for (int b=0;b<4;b++)
#pragma unroll
      for (int c=0;c<4;c++) acc[a][b][c]=0.f;

  auto issue = [&](int slot, int kb){
    char* sb = sm + slot*RSLOT;
#pragma unroll
    for (int s=0;s<2;s++){
      int seg = tid + s*256;
      int row = seg >> 2, sc = seg & 3;
      cp16(sb + row*SRS + sc*16, A + (size_t)(m0 + row)*K + kb + sc*8);
    }
#pragma unroll
    for (int s=0;s<4;s++){
      int seg = tid + s*256;
      int row = seg >> 3, sc = seg & 7;
      int gn = n0 + row; if (gn > Ntot-1) gn = Ntot-1;
      cp16(sb + ARB + row*128 + sc*16, B + (size_t)gn*K + kb + sc*4);
    }
    cp_commit();
  };
  auto conv = [&](int c){
    char* src = sm + (c%3)*RSLOT + ARB;
    char* dst = sm + F16OFF + (c&1)*F16B;
#pragma unroll
    for (int s=0;s<2;s++){
      int unit = tid + s*256;
      int row = unit >> 2, sc = unit & 3;
      const float4* p = reinterpret_cast<const float4*>(src + row*128 + sc*32);
      float4 a = p[0], b = p[1];
      union { uint4 u; __half2 h[4]; } o;
      o.h[0] = __floats2half2_rn(a.x, a.y);
      o.h[1] = __floats2half2_rn(a.z, a.w);
      o.h[2] = __floats2half2_rn(b.x, b.y);
      o.h[3] = __floats2half2_rn(b.z, b.w);
      *reinterpret_cast<uint4*>(dst + row*SRS + sc*16) = o.u;
    }
  };
  auto do_mma = [&](int c){
    char* sa = sm + (c%3)*RSLOT;
    char* sb = sm + F16OFF + (c&1)*F16B;
    const int ar = lane & 15, ac = (lane >> 4) * 8;
    const int q = lane >> 3, rq = lane & 7;
    const int bro = ((q>>1)*8 + rq)*SRS + (q&1)*16;
#pragma unroll
    for (int ks=0; ks<2; ks++){
      const int kk = ks*16;
      uint32_t af[4][4], bf[8];
#pragma unroll
      for (int ms=0; ms<4; ms++)
        ldsm4(af[ms], sa + (wm + ms*16 + ar)*SRS + (kk + ac)*2);
#pragma unroll
      for (int nsp=0; nsp<2; nsp++)
        ldsm4(bf + nsp*4, sb + (wn + nsp*16)*SRS + kk*2 + bro);
#pragma unroll
      for (int ms=0; ms<4; ms++)
#pragma unroll
        for (int ns=0; ns<4; ns++)
          mma_fp16(acc[ms][ns], af[ms], bf + ns*2);
    }
  };

  issue(0, 0);
  issue(1, BK);
  cp_wait1();
  __syncthreads();
  conv(0);

  for (int i=0; i<nch; i++){
    __syncthreads();
    if (i+2 < nch) issue((i+2)%3, (i+2)*BK);
    do_mma(i);
    if (i+1 < nch){
      if (i+2 < nch) cp_wait1(); else cp_wait0();
      __syncthreads();
      conv(i+1);
    }
  }

  const int gr = lane >> 2, gc = (lane & 3) * 2;
#pragma unroll
  for (int ms=0; ms<4; ms++)
#pragma unroll
    for (int ns=0; ns<4; ns++){
      int row = m0 + wm + ms*16 + gr;
      int col = n0 + wn + ns*8 + gc;
      if (col < Ntot){
        *reinterpret_cast<float2*>(&C[(size_t)row*Ntot + col])     = make_float2(acc[ms][ns][0], acc[ms][ns][1]);
        *reinterpret_cast<float2*>(&C[(size_t)(row+8)*Ntot + col]) = make_float2(acc[ms][ns][2], acc[ms][ns][3]);
      }
    }
}

// ---------------- small kernels ----------------
// warp-per-row normalize
__global__ void rownorm_h(const float* __restrict__ img, const float* __restrict__ ls,
                          __half* __restrict__ outh){
  int warp = threadIdx.x >> 5, lane = threadIdx.x & 31;
  int row = blockIdx.x*8 + warp;
  float v[16]; float s = 0.f;
#pragma unroll
  for (int j=0;j<16;j++){ v[j] = img[row*D_OUTF + lane + j*32]; s += v[j]*v[j]; }
#pragma unroll
  for (int off=16; off>0; off>>=1) s += __shfl_xor_sync(0xffffffffu, s, off);
  float sc = expf(*ls) * rsqrtf(s);
#pragma unroll
  for (int j=0;j<16;j++)
    outh[row*D_OUTF + lane + j*32] = __float2half_rn(v[j]*sc);
}

// topk phase 1: 100 blocks x 256 threads; values cached in registers (1 gmem pass)
__global__ void topk_p1(const float* __restrict__ logits){
  __shared__ float rv[256];
  __shared__ int   ri[256];
  __shared__ int   sel[TOPK];
  __shared__ float bmax_s;
  int t = threadIdx.x, b = blockIdx.x;
  int lo = b*1000, hi = lo + 1000;

  float vc[4]; int ic[4]; int myn = 0;
  for (int i = lo + t; i < hi; i += 256){ vc[myn] = logits[i]; ic[myn] = i; myn++; }

  float m = -3.4e38f;
  for (int j=0;j<myn;j++) m = fmaxf(m, vc[j]);
  rv[t] = m; __syncthreads();
  for (int s=128; s>0; s>>=1){ if (t<s) rv[t]=fmaxf(rv[t],rv[t+s]); __syncthreads(); }
  if (t==0) bmax_s = rv[0];
  __syncthreads();
  float bm = bmax_s;

  float sum = 0.f;
  for (int j=0;j<myn;j++) sum += expf(vc[j] - bm);
  rv[t] = sum; __syncthreads();
  for (int s=128; s>0; s>>=1){ if (t<s) rv[t]+=rv[t+s]; __syncthreads(); }
  if (t==0){ g_pmax[b] = bm; g_psum[b] = rv[0]; }
  __syncthreads();

  for (int r = 0; r < TOPK; r++){
    float bv = -3.4e38f; int bi = 0x7fffffff;
    for (int j=0;j<myn;j++){
      bool skip = false;
#pragma unroll
      for (int u = 0; u < TOPK; u++) if (u < r && sel[u] == ic[j]) skip = true;
      if (!skip && (vc[j] > bv || (vc[j] == bv && ic[j] < bi))){ bv = vc[j]; bi = ic[j]; }
    }
    rv[t] = bv; ri[t] = bi; __syncthreads();
    for (int s=128; s>0; s>>=1){
      if (t<s){
        if (rv[t+s] > rv[t] || (rv[t+s] == rv[t] && ri[t+s] < ri[t])){
          rv[t]=rv[t+s]; ri[t]=ri[t+s];
        }
      }
      __syncthreads();
    }
    if (t==0){ sel[r] = ri[0]; g_pidx[b*TOPK + r] = ri[0]; g_pval[b*TOPK + r] = rv[0]; }
    __syncthreads();
  }
}

// topk phase 2: merge 100 partials, write gps + probs tail
__global__ void topk_p2(const float* __restrict__ gps, float* __restrict__ out_tail){
  __shared__ float rv[512];
  __shared__ int   ri[512];
  __shared__ float gM_s, gS_s;
  int t = threadIdx.x;

  float m = (t < 100) ? g_pmax[t] : -3.4e38f;
  rv[t] = m; __syncthreads();
  for (int s=256; s>0; s>>=1){ if (t<s) rv[t]=fmaxf(rv[t],rv[t+s]); __syncthreads(); }
  if (t==0) gM_s = rv[0];
  __syncthreads();
  float M = gM_s;

  float sum = (t < 100) ? g_psum[t] * expf(g_pmax[t] - M) : 0.f;
  rv[t] = sum; __syncthreads();
  for (int s=256; s>0; s>>=1){ if (t<s) rv[t]+=rv[t+s]; __syncthreads(); }
  if (t==0) gS_s = rv[0];
  __syncthreads();
  float S = gS_s;

  float cv = (t < 100*TOPK) ? g_pval[t] : -3.4e38f;
  int   ci = (t < 100*TOPK) ? g_pidx[t] : 0x7fffffff;

  for (int r = 0; r < TOPK; r++){
    rv[t] = cv; ri[t] = ci; __syncthreads();
    for (int s=256; s>0; s>>=1){
      if (t<s){
        if (rv[t+s] > rv[t] || (rv[t+s] == rv[t] && ri[t+s] < ri[t])){
          rv[t]=rv[t+s]; ri[t]=ri[t+s];
        }
      }
      __syncthreads();
    }
    if (t == 0){
      int gi = ri[0];
      out_tail[2*r]   = gps[2*gi];
      out_tail[2*r+1] = gps[2*gi+1];
      out_tail[2*TOPK + r] = expf(rv[0] - M) / S;
    }
    __syncthreads();
    if (ci == ri[0]) cv = -3.4e38f;
    __syncthreads();
  }
}

extern "C" void kernel_launch(void* const* d_in, const int* in_sizes, int n_in,
                              void* d_out, int out_size){
  const float* img_feats   = (const float*)d_in[0];
  const float* w1          = (const float*)d_in[1];
  const float* b1          = (const float*)d_in[2];
  const float* w2          = (const float*)d_in[3];
  const float* b2          = (const float*)d_in[4];
  const float* logit_scale = (const float*)d_in[5];
  const float* loc_feats   = (const float*)d_in[6];
  const float* gps         = (const float*)d_in[7];
  float* out = (float*)d_out;

  void *ahi2,*alo2,*imgb,*an;
  cudaGetSymbolAddress(&ahi2, g_Ahi2);
  cudaGetSymbolAddress(&alo2, g_Alo2);
  cudaGetSymbolAddress(&imgb, g_IMG);
  cudaGetSymbolAddress(&an,   g_AN);

  cudaFuncSetAttribute(mlpgemm<true,true,true>,    cudaFuncAttributeMaxDynamicSharedMemorySize, 55296);
  cudaFuncSetAttribute(mlpgemm<false,false,false>, cudaFuncAttributeMaxDynamicSharedMemorySize, 55296);
  cudaFuncSetAttribute(hgemmBig,                   cudaFuncAttributeMaxDynamicSharedMemorySize, 100352);

  // 1) H = relu(X W1^T + b1): A f32 converted in-kernel; epilogue writes fp16 hi/lo
  mlpgemm<true,true,true><<<dim3(N_IMG/32, D_HID/64), 256, 55296>>>(
      img_feats, nullptr, nullptr, w1, b1, nullptr, (__half*)ahi2, (__half*)alo2, D_HID, D_INF);
  // 2) IMG = H W2^T + b2 (f32 out)
  mlpgemm<false,false,false><<<dim3(N_IMG/32, D_OUTF/64), 256, 55296>>>(
      nullptr, (__half*)ahi2, (__half*)alo2, w2, b2, (float*)imgb, nullptr, nullptr, D_OUTF, D_HID);
  // 3) normalize rows, fold in exp(logit_scale) -> single fp16
  rownorm_h<<<N_IMG/8,256>>>((const float*)imgb, logit_scale, (__half*)an);
  // 4) logits = (s*img_n) @ loc_feats^T (launch #4 -> ncu capture target)
  hgemmBig<<<dim3(2, (M_GAL+127)/128), 256, 100352>>>(
      (__half*)an, loc_feats, out, M_GAL, D_OUTF);
  // 5) row-0 softmax + top-5
  topk_p1<<<100,256>>>(out);
  topk_p2<<<1,512>>>(gps, out + (size_t)N_IMG*M_GAL);
}

// round 14
// speedup vs baseline: 1.1384x; 1.1278x over previous
#include <cuda_runtime.h>
#include <cuda_fp16.h>
#include <cstdint>

#define DEV __device__ __forceinline__

// problem dims
#define N_IMG 256
#define D_INF 768
#define D_HID 768
#define D_OUTF 512
#define M_GAL 100000
#define TOPK 5

// scratch (no cudaMalloc allowed)
__device__ __half g_Ahi2[N_IMG*D_HID];
__device__ __half g_Alo2[N_IMG*D_HID];
__device__ float  g_IMG [N_IMG*D_OUTF];
__device__ __half g_AN  [N_IMG*D_OUTF];
// topk scratch
__device__ float g_pmax[100];
__device__ float g_psum[100];
__device__ int   g_pidx[100*TOPK];
__device__ float g_pval[100*TOPK];

DEV void cp16(void* s, const void* g){
  uint32_t sa = (uint32_t)__cvta_generic_to_shared(s);
  asm volatile("cp.async.cg.shared.global [%0], [%1], 16;" :: "r"(sa), "l"(g));
}
DEV void cp_commit(){ asm volatile("cp.async.commit_group;"); }
DEV void cp_wait0(){ asm volatile("cp.async.wait_group 0;"); }

DEV void ldsm4(uint32_t* d, const void* p){
  uint32_t a=(uint32_t)__cvta_generic_to_shared(p);
  asm volatile("ldmatrix.sync.aligned.m8n8.x4.shared.b16 {%0,%1,%2,%3}, [%4];"
    : "=r"(d[0]),"=r"(d[1]),"=r"(d[2]),"=r"(d[3]) : "r"(a));
}
DEV void mma_fp16(float* c, const uint32_t* a, const uint32_t* b){
  asm volatile("mma.sync.aligned.m16n8k16.row.col.f32.f16.f16.f32 "
    "{%0,%1,%2,%3}, {%4,%5,%6,%7}, {%8,%9}, {%0,%1,%2,%3};"
    : "+f"(c[0]),"+f"(c[1]),"+f"(c[2]),"+f"(c[3])
    : "r"(a[0]),"r"(a[1]),"r"(a[2]),"r"(a[3]),"r"(b[0]),"r"(b[1]));
}

// ===== MLP GEMM (round-12 proven): 3-term fp16, BM=32 BN=64 BK=64, 2-stage =====
template<bool A_F32, bool RELU, bool SPLIT>
__global__ __launch_bounds__(256, 2)
void mlpgemm(const float* __restrict__ Af, const __half* __restrict__ Ahi, const __half* __restrict__ Alo,
             const float* __restrict__ B, const float* __restrict__ bias,
             float* __restrict__ Cf, __half* __restrict__ Chi, __half* __restrict__ Clo,
             int Ntot, int K){
  constexpr int SABB = 144;
  constexpr int ABY  = 32*SABB;
  constexpr int OB   = 2*ABY;
  constexpr int BBY  = 64*SABB;
  constexpr int STAGE= OB + 2*BBY;   // 27648 ; x2 = 55296

  extern __shared__ __align__(16) char sm[];
  const int tid = threadIdx.x, lane = tid & 31, warp = tid >> 5;
  const int wm = (warp & 1) * 16, wn = (warp >> 1) * 16;
  const int m0 = blockIdx.x * 32, n0 = blockIdx.y * 64;
  const int nch = K / 64;

  float acc[2][4];
#pragma unroll
  for (int b=0;b<2;b++)
#pragma unroll
    for (int c=0;c<4;c++) acc[b][c]=0.f;

  float4 breg[2][2];
  float4 areg[2];
  auto loadB = [&](int kb){
#pragma unroll
    for (int s=0;s<2;s++){
      int seg = tid + s*256;
      int row = seg >> 3, sc = seg & 7;
      const float4* p = reinterpret_cast<const float4*>(B + (size_t)(n0+row)*K + kb + sc*8);
      breg[s][0] = p[0]; breg[s][1] = p[1];
    }
  };
  auto loadA = [&](int kb){
    int row = tid >> 3, sc = tid & 7;
    const float4* p = reinterpret_cast<const float4*>(Af + (size_t)(m0+row)*K + kb + sc*8);
    areg[0] = p[0]; areg[1] = p[1];
  };
  auto split8 = [&](const float4& a, const float4& b, uint4& uh, uint4& ul){
    float f[8] = {a.x,a.y,a.z,a.w,b.x,b.y,b.z,b.w};
    union { uint4 u; __half h[8]; } ph, pl;
#pragma unroll
    for (int e=0;e<8;e++){
      __half hh = __float2half_rn(f[e]);
      ph.h[e] = hh;
      pl.h[e] = __float2half_rn(f[e] - __half2float(hh));
    }
    uh = ph.u; ul = pl.u;
  };
  auto stsB = [&](int buf){
#pragma unroll
    for (int s=0;s<2;s++){
      int seg = tid + s*256;
      int row = seg >> 3, sc = seg & 7;
      uint4 uh, ul;
      split8(breg[s][0], breg[s][1], uh, ul);
      char* dst = sm + buf*STAGE + OB + row*SABB + sc*16;
      *reinterpret_cast<uint4*>(dst)       = uh;
      *reinterpret_cast<uint4*>(dst + BBY) = ul;
    }
  };
  auto stsA = [&](int buf){
    int row = tid >> 3, sc = tid & 7;
    uint4 uh, ul;
    split8(areg[0], areg[1], uh, ul);
    char* dst = sm + buf*STAGE + row*SABB + sc*16;
    *reinterpret_cast<uint4*>(dst)       = uh;
    *reinterpret_cast<uint4*>(dst + ABY) = ul;
  };
  auto cpA = [&](int buf, int kb){
    int row = tid >> 3, sc = tid & 7;
    size_t go = (size_t)(m0 + row)*K + kb + sc*8;
    char* d = sm + buf*STAGE + row*SABB + sc*16;
    cp16(d,       Ahi + go);
    cp16(d + ABY, Alo + go);
  };
  auto do_mma = [&](int buf){
    char* sa  = sm + buf*STAGE;
    char* sbh = sa + OB;
    const int ar = lane & 15, ac = (lane >> 4) * 8;
    const int q = lane >> 3, rq = lane & 7;
    const int bro = ((q>>1)*8 + rq)*SABB + (q&1)*16;
#pragma unroll
    for (int ks=0; ks<4; ks++){
      const int kk = ks*16;
      uint32_t ah[4], al[4], bh[4], bl[4];
      char* pa = sa + (wm + ar)*SABB + (kk + ac)*2;
      ldsm4(ah, pa);
      ldsm4(al, pa + ABY);
      char* pb = sbh + wn*SABB + kk*2 + bro;
      ldsm4(bh, pb);
      ldsm4(bl, pb + BBY);
#pragma unroll
      for (int ns=0; ns<2; ns++){
        mma_fp16(acc[ns], ah, bh + ns*2);
        mma_fp16(acc[ns], al, bh + ns*2);
        mma_fp16(acc[ns], ah, bl + ns*2);
      }
    }
  };

  loadB(0); if (A_F32) loadA(0);
  stsB(0);  if (A_F32) stsA(0);
  if (!A_F32){ cpA(0, 0); cp_commit(); }

  for (int i=0; i<nch; i++){
    const int buf = i & 1;
    if (i+1 < nch){ loadB((i+1)*64); if (A_F32) loadA((i+1)*64); }
    if (!A_F32) cp_wait0();
    __syncthreads();
    if (!A_F32 && i+1 < nch){ cpA(buf^1, (i+1)*64); cp_commit(); }
    do_mma(buf);
    if (i+1 < nch){ stsB(buf^1); if (A_F32) stsA(buf^1); }
  }

  const int gr = lane >> 2, gc = (lane & 3) * 2;
#pragma unroll
  for (int ns=0; ns<2; ns++){
    int row = m0 + wm + gr;
    int col = n0 + wn + ns*8 + gc;
    float v0=acc[ns][0], v1=acc[ns][1], v2=acc[ns][2], v3=acc[ns][3];
    float c0=bias[col], c1=bias[col+1];
    v0+=c0; v1+=c1; v2+=c0; v3+=c1;
    if (RELU){ v0=fmaxf(v0,0.f); v1=fmaxf(v1,0.f); v2=fmaxf(v2,0.f); v3=fmaxf(v3,0.f); }
    if (SPLIT){
      __half h0=__float2half_rn(v0), h1=__float2half_rn(v1);
      __half h2=__float2half_rn(v2), h3=__float2half_rn(v3);
      *reinterpret_cast<__half2*>(&Chi[(size_t)row*Ntot + col])     = __halves2half2(h0,h1);
      *reinterpret_cast<__half2*>(&Chi[(size_t)(row+8)*Ntot + col]) = __halves2half2(h2,h3);
      *reinterpret_cast<__half2*>(&Clo[(size_t)row*Ntot + col]) =
          __halves2half2(__float2half_rn(v0-__half2float(h0)), __float2half_rn(v1-__half2float(h1)));
      *reinterpret_cast<__half2*>(&Clo[(size_t)(row+8)*Ntot + col]) =
          __halves2half2(__float2half_rn(v2-__half2float(h2)), __float2half_rn(v3-__half2float(h3)));
    } else {
      *reinterpret_cast<float2*>(&Cf[(size_t)row*Ntot + col])     = make_float2(v0,v1);
      *reinterpret_cast<float2*>(&Cf[(size_t)(row+8)*Ntot + col]) = make_float2(v2,v3);
    }
  }
}

// ===== big GEMM v3 (indexing fixed): B via LDG->regs->STS f16, BM128 BN128 BK32 =====
// smem: A 2-stage cp.async (2x10240) + B f16 2-slot (2x10240) = 40960. 2 CTA/SM.
__global__ __launch_bounds__(256, 2)
void hgemmBig(const __half* __restrict__ A, const float* __restrict__ B,
              float* __restrict__ C, int Ntot, int K){
  constexpr int SRS  = 80;                  // f16 row stride (32 halfs + 16B pad)
  constexpr int ABY  = 128*SRS;             // 10240 per A stage
  constexpr int BOFF = 2*ABY;               // 20480 : B f16 slots
  constexpr int BBY  = 128*SRS;             // 10240 per B slot
  constexpr int BK   = 32;

  extern __shared__ __align__(16) char sm[];
  const int tid = threadIdx.x, lane = tid & 31, warp = tid >> 5;
  const int wm = (warp & 1) * 64, wn = (warp >> 1) * 32;   // 2x4 warps, 64x32 tiles
  const int m0 = blockIdx.x * 128, n0 = blockIdx.y * 128;
  const int nch = K / BK;                   // 16

  float acc[4][4][4];
#pragma unroll
  for (int a=0;a<4;a++)
#pragma unroll
    for (int b=0;b<4;b++)
#pragma unroll
      for (int c=0;c<4;c++) acc[a][b][c]=0.f;

  float4 breg[4];
  // FIX (round-13 bug): BK=32 f32 row = 128B = 8 float4 segments.
  // 128 rows x 8 segs = 1024 units -> row = seg>>3, q = seg&7.
  // Round 13 used seg>>2/seg&3: rows ran to 255 -> stsB wrote past smem (illegal access)
  // and only half of each row's columns were loaded.
  auto loadB = [&](int kb){
#pragma unroll
    for (int s=0;s<4;s++){
      int seg = tid + s*256;
      int row = seg >> 3, q = seg & 7;
      int gn = n0 + row; if (gn > Ntot-1) gn = Ntot-1;
      breg[s] = *reinterpret_cast<const float4*>(B + (size_t)gn*K + kb + q*4);
    }
  };
  auto stsB = [&](int slot){
    char* dst0 = sm + BOFF + slot*BBY;
#pragma unroll
    for (int s=0;s<4;s++){
      int seg = tid + s*256;
      int row = seg >> 3, q = seg & 7;
      union { uint2 u; __half2 h[2]; } o;
      o.h[0] = __floats2half2_rn(breg[s].x, breg[s].y);
      o.h[1] = __floats2half2_rn(breg[s].z, breg[s].w);
      *reinterpret_cast<uint2*>(dst0 + row*SRS + q*8) = o.u;   // 8 f16-bytes per float4; max 56+8=64 <= SRS
    }
  };
  auto cpA = [&](int buf, int kb){
    // A fp16: 128 rows x 4 x 16B = 512 segs (2/thread)
#pragma unroll
    for (int s=0;s<2;s++){
      int seg = tid + s*256;
      int row = seg >> 2, sc = seg & 3;
      cp16(sm + buf*ABY + row*SRS + sc*16, A + (size_t)(m0 + row)*K + kb + sc*8);
    }
    cp_commit();
  };
  auto do_mma = [&](int i){
    char* sa = sm + (i&1)*ABY;
    char* sb = sm + BOFF + (i&1)*BBY;
    const int ar = lane & 15, ac = (lane >> 4) * 8;
    const int q = lane >> 3, rq = lane & 7;
    const int bro = ((q>>1)*8 + rq)*SRS + (q&1)*16;
#pragma unroll
    for (int ks=0; ks<2; ks++){
      const int kk = ks*16;
      uint32_t af[4][4], bf[8];
#pragma unroll
      for (int ms=0; ms<4; ms++)
        ldsm4(af[ms], sa + (wm + ms*16 + ar)*SRS + (kk + ac)*2);
#pragma unroll
      for (int nsp=0; nsp<2; nsp++)
        ldsm4(bf + nsp*4, sb + (wn + nsp*16)*SRS + kk*2 + bro);
#pragma unroll
      for (int ms=0; ms<4; ms++)
#pragma unroll
        for (int ns=0; ns<4; ns++)
          mma_fp16(acc[ms][ns], af[ms], bf + ns*2);
    }
  };

  // prologue: chunk 0 B in smem; A chunk 0 in flight
  loadB(0);
  stsB(0);
  cpA(0, 0);

  for (int i=0; i<nch; i++){
    const int buf = i & 1;
    if (i+1 < nch) loadB((i+1)*BK);   // LDGs for next chunk; consumed after mma(i)
    cp_wait0();                        // A chunk i resident (this thread's view)
    __syncthreads();                   // all threads: A(i)+B(i) visible; mma(i-1)+stsB(i) retired
    if (i+1 < nch) cpA(buf^1, (i+1)*BK);
    do_mma(i);                         // covers LDG latency of loadB(i+1)
    if (i+1 < nch) stsB(buf^1);        // slot (i+1)&1; mma(i-1) that read it retired at sync
  }

  const int gr = lane >> 2, gc = (lane & 3) * 2;
#pragma unroll
  for (int ms=0; ms<4; ms++)
#pragma unroll
    for (int ns=0; ns<4; ns++){
      int row = m0 + wm + ms*16 + gr;
      int col = n0 + wn + ns*8 + gc;
      if (col < Ntot){
        *reinterpret_cast<float2*>(&C[(size_t)row*Ntot + col])     = make_float2(acc[ms][ns][0], acc[ms][ns][1]);
        *reinterpret_cast<float2*>(&C[(size_t)(row+8)*Ntot + col]) = make_float2(acc[ms][ns][2], acc[ms][ns][3]);
      }
    }
}

// ---------------- small kernels (round-12 proven) ----------------
__global__ void rownorm_h(const float* __restrict__ img, const float* __restrict__ ls,
                          __half* __restrict__ outh){
  int warp = threadIdx.x >> 5, lane = threadIdx.x & 31;
  int row = blockIdx.x*8 + warp;
  float v[16]; float s = 0.f;
#pragma unroll
  for (int j=0;j<16;j++){ v[j] = img[row*D_OUTF + lane + j*32]; s += v[j]*v[j]; }
#pragma unroll
  for (int off=16; off>0; off>>=1) s += __shfl_xor_sync(0xffffffffu, s, off);
  float sc = expf(*ls) * rsqrtf(s);
#pragma unroll
  for (int j=0;j<16;j++)
    outh[row*D_OUTF + lane + j*32] = __float2half_rn(v[j]*sc);
}

__global__ void topk_p1(const float* __restrict__ logits){
  __shared__ float rv[256];
  __shared__ int   ri[256];
  __shared__ int   sel[TOPK];
  __shared__ float bmax_s;
  int t = threadIdx.x, b = blockIdx.x;
  int lo = b*1000, hi = lo + 1000;

  float vc[4]; int ic[4]; int myn = 0;
  for (int i = lo + t; i < hi; i += 256){ vc[myn] = logits[i]; ic[myn] = i; myn++; }

  float m = -3.4e38f;
  for (int j=0;j<myn;j++) m = fmaxf(m, vc[j]);
  rv[t] = m; __syncthreads();
  for (int s=128; s>0; s>>=1){ if (t<s) rv[t]=fmaxf(rv[t],rv[t+s]); __syncthreads(); }
  if (t==0) bmax_s = rv[0];
  __syncthreads();
  float bm = bmax_s;

  float sum = 0.f;
  for (int j=0;j<myn;j++) sum += expf(vc[j] - bm);
  rv[t] = sum; __syncthreads();
  for (int s=128; s>0; s>>=1){ if (t<s) rv[t]+=rv[t+s]; __syncthreads(); }
  if (t==0){ g_pmax[b] = bm; g_psum[b] = rv[0]; }
  __syncthreads();

  for (int r = 0; r < TOPK; r++){
    float bv = -3.4e38f; int bi = 0x7fffffff;
    for (int j=0;j<myn;j++){
      bool skip = false;
#pragma unroll
      for (int u = 0; u < TOPK; u++) if (u < r && sel[u] == ic[j]) skip = true;
      if (!skip && (vc[j] > bv || (vc[j] == bv && ic[j] < bi))){ bv = vc[j]; bi = ic[j]; }
    }
    rv[t] = bv; ri[t] = bi; __syncthreads();
    for (int s=128; s>0; s>>=1){
      if (t<s){
        if (rv[t+s] > rv[t] || (rv[t+s] == rv[t] && ri[t+s] < ri[t])){
          rv[t]=rv[t+s]; ri[t]=ri[t+s];
        }
      }
      __syncthreads();
    }
    if (t==0){ sel[r] = ri[0]; g_pidx[b*TOPK + r] = ri[0]; g_pval[b*TOPK + r] = rv[0]; }
    __syncthreads();
  }
}

__global__ void topk_p2(const float* __restrict__ gps, float* __restrict__ out_tail){
  __shared__ float rv[512];
  __shared__ int   ri[512];
  __shared__ float gM_s, gS_s;
  int t = threadIdx.x;

  float m = (t < 100) ? g_pmax[t] : -3.4e38f;
  rv[t] = m; __syncthreads();
  for (int s=256; s>0; s>>=1){ if (t<s) rv[t]=fmaxf(rv[t],rv[t+s]); __syncthreads(); }
  if (t==0) gM_s = rv[0];
  __syncthreads();
  float M = gM_s;

  float sum = (t < 100) ? g_psum[t] * expf(g_pmax[t] - M) : 0.f;
  rv[t] = sum; __syncthreads();
  for (int s=256; s>0; s>>=1){ if (t<s) rv[t]+=rv[t+s]; __syncthreads(); }
  if (t==0) gS_s = rv[0];
  __syncthreads();
  float S = gS_s;

  float cv = (t < 100*TOPK) ? g_pval[t] : -3.4e38f;
  int   ci = (t < 100*TOPK) ? g_pidx[t] : 0x7fffffff;

  for (int r = 0; r < TOPK; r++){
    rv[t] = cv; ri[t] = ci; __syncthreads();
    for (int s=256; s>0; s>>=1){
      if (t<s){
        if (rv[t+s] > rv[t] || (rv[t+s] == rv[t] && ri[t+s] < ri[t])){
          rv[t]=rv[t+s]; ri[t]=ri[t+s];
        }
      }
      __syncthreads();
    }
    if (t == 0){
      int gi = ri[0];
      out_tail[2*r]   = gps[2*gi];
      out_tail[2*r+1] = gps[2*gi+1];
      out_tail[2*TOPK + r] = expf(rv[0] - M) / S;
    }
    __syncthreads();
    if (ci == ri[0]) cv = -3.4e38f;
    __syncthreads();
  }
}

extern "C" void kernel_launch(void* const* d_in, const int* in_sizes, int n_in,
                              void* d_out, int out_size){
  const float* img_feats   = (const float*)d_in[0];
  const float* w1          = (const float*)d_in[1];
  const float* b1          = (const float*)d_in[2];
  const float* w2          = (const float*)d_in[3];
  const float* b2          = (const float*)d_in[4];
  const float* logit_scale = (const float*)d_in[5];
  const float* loc_feats   = (const float*)d_in[6];
  const float* gps         = (const float*)d_in[7];
  float* out = (float*)d_out;

  void *ahi2,*alo2,*imgb,*an;
  cudaGetSymbolAddress(&ahi2, g_Ahi2);
  cudaGetSymbolAddress(&alo2, g_Alo2);
  cudaGetSymbolAddress(&imgb, g_IMG);
  cudaGetSymbolAddress(&an,   g_AN);

  cudaFuncSetAttribute(mlpgemm<true,true,true>,    cudaFuncAttributeMaxDynamicSharedMemorySize, 55296);
  cudaFuncSetAttribute(mlpgemm<false,false,false>, cudaFuncAttributeMaxDynamicSharedMemorySize, 55296);
  cudaFuncSetAttribute(hgemmBig,                   cudaFuncAttributeMaxDynamicSharedMemorySize, 40960);

  // 1) H = relu(X W1^T + b1)
  mlpgemm<true,true,true><<<dim3(N_IMG/32, D_HID/64), 256, 55296>>>(
      img_feats, nullptr, nullptr, w1, b1, nullptr, (__half*)ahi2, (__half*)alo2, D_HID, D_INF);
  // 2) IMG = H W2^T + b2
  mlpgemm<false,false,false><<<dim3(N_IMG/32, D_OUTF/64), 256, 55296>>>(
      nullptr, (__half*)ahi2, (__half*)alo2, w2, b2, (float*)imgb, nullptr, nullptr, D_OUTF, D_HID);
  // 3) normalize rows, fold in exp(logit_scale)
  rownorm_h<<<N_IMG/8,256>>>((const float*)imgb, logit_scale, (__half*)an);
  // 4) logits = (s*img_n) @ loc_feats^T — LDG-direct B, no f32 staging
  hgemmBig<<<dim3(2, (M_GAL+127)/128), 256, 40960>>>(
      (__half*)an, loc_feats, out, M_GAL, D_OUTF);
  // 5) row-0 softmax + top-5
  topk_p1<<<100,256>>>(out);
  topk_p2<<<1,512>>>(gps, out + (size_t)N_IMG*M_GAL);
}